// round 9
// baseline (speedup 1.0000x reference)
#include <cuda_runtime.h>
#include <cuda_bf16.h>
#include <stdint.h>
#include <math.h>

// Problem constants (fixed by the reference)
#define BATCH 8
#define CH    512
#define HW    1024       // 32*32 spatial
#define NG    32
#define CPG   16
#define GRP_ELEMS (CPG*HW)   // 16384

typedef __nv_bfloat16 bf16;

// ---------------- scratch (static device globals; no allocation) -------------
__device__ bf16  g_xnT   [BATCH * HW * CH];        // xn^T  [b][pix][c]
__device__ bf16  g_qkT   [BATCH * HW * 2 * CH];    // [b][i][0..511]=Q, [512..1023]=K
__device__ bf16  g_v     [BATCH * CH * HW];        // V     [b][c][j]
__device__ float g_attn  [BATCH * HW * HW];        // scores fp32 [b][i][j]
__device__ bf16  g_attnbf[BATCH * HW * HW];        // softmaxed, bf16
__device__ bf16  g_aoutT [BATCH * HW * CH];        // out^T [b][i][c]
__device__ bf16  g_wbf   [3 * CH * CH];            // qkv_w bf16
__device__ bf16  g_pwbf  [CH * CH];                // proj_w bf16

// ---------------- helpers -----------------------------------------------------
__device__ __forceinline__ uint32_t packbf(float x, float y) {
    __nv_bfloat162 h = __float22bfloat162_rn(make_float2(x, y));
    return *(uint32_t*)&h;
}
__device__ __forceinline__ uint32_t smem_u32(const void* p) {
    return (uint32_t)__cvta_generic_to_shared(p);
}
#define CP_ASYNC16(dst, src) \
    asm volatile("cp.async.cg.shared.global [%0], [%1], 16;\n" :: "r"(dst), "l"(src))
#define CP_COMMIT()  asm volatile("cp.async.commit_group;\n" ::)
#define CP_WAIT2()   asm volatile("cp.async.wait_group 2;\n" ::)

// ---------------- weight conversion f32 -> bf16 ------------------------------
__global__ void tobf16_kernel(const float* __restrict__ in, bf16* __restrict__ out, int n4)
{
    int i = blockIdx.x * blockDim.x + threadIdx.x;
    if (i < n4) {
        float4 v = ((const float4*)in)[i];
        uint2 o = make_uint2(packbf(v.x, v.y), packbf(v.z, v.w));
        ((uint2*)out)[i] = o;
    }
}

// ---------------- GroupNorm (writes transposed bf16 xnT) ---------------------
__global__ __launch_bounds__(256)
void groupnorm_t_kernel(const float* __restrict__ x,
                        const float* __restrict__ w,
                        const float* __restrict__ bias,
                        bf16* __restrict__ xnT)
{
    const int bg = blockIdx.x;
    const int b  = bg / NG;
    const int g  = bg % NG;
    const float* xp = x + ((size_t)b * CH + (size_t)g * CPG) * HW;

    const int tid = threadIdx.x;
    float sum = 0.f, sq = 0.f;
    for (int i = tid; i < GRP_ELEMS; i += 256) {
        float v = xp[i];
        sum += v; sq += v * v;
    }
    __shared__ float ssum[8], ssq[8];
    int lane = tid & 31, wid = tid >> 5;
    #pragma unroll
    for (int o = 16; o > 0; o >>= 1) {
        sum += __shfl_xor_sync(0xffffffffu, sum, o);
        sq  += __shfl_xor_sync(0xffffffffu, sq,  o);
    }
    if (lane == 0) { ssum[wid] = sum; ssq[wid] = sq; }
    __syncthreads();
    if (wid == 0) {
        sum = ssum[lane & 7];
        sq  = ssq [lane & 7];
        #pragma unroll
        for (int o = 4; o > 0; o >>= 1) {
            sum += __shfl_xor_sync(0xffffffffu, sum, o);
            sq  += __shfl_xor_sync(0xffffffffu, sq,  o);
        }
        if (lane == 0) { ssum[0] = sum; ssq[0] = sq; }
    }
    __syncthreads();
    const float inv_n = 1.f / (float)GRP_ELEMS;
    const float mean  = ssum[0] * inv_n;
    const float var   = ssq[0] * inv_n - mean * mean;
    const float rstd  = rsqrtf(var + 1e-5f);

    __shared__ float tile[CPG][64 + 1];
    for (int pt = 0; pt < 16; pt++) {
        __syncthreads();
        #pragma unroll
        for (int j = 0; j < 4; j++) {
            int e = tid + j * 256;
            int c = e >> 6, p = e & 63;
            float v = xp[c * HW + pt * 64 + p];
            tile[c][p] = (v - mean) * rstd * w[g * CPG + c] + bias[g * CPG + c];
        }
        __syncthreads();
        int p = tid >> 2, cq = tid & 3;
        uint2 o = make_uint2(packbf(tile[cq * 4 + 0][p], tile[cq * 4 + 1][p]),
                             packbf(tile[cq * 4 + 2][p], tile[cq * 4 + 3][p]));
        *(uint2*)&xnT[((size_t)b * HW + pt * 64 + p) * CH + g * CPG + cq * 4] = o;
    }
}

// ---------------- pipelined bf16 tensor-core GEMM ----------------------------
// C[b][m][n] = alpha * sum_k A[m][k]*B[n][k]  (+biasM[m]) (+biasN[n]) (+res)
// A bf16 [M x K] (lda), B bf16 [N x K] (ldb), C (ldc = N) fp32 or bf16.
// Tiles BM=BN=128, BK=32; 8 warps (2M x 4N), warp tile 64x32, mma.m16n8k16.
// 4-stage cp.async ring, ONE __syncthreads per iteration:
//   iter kt: wait_group 2 -> sync -> prefetch chunk kt+3 into stage (kt-1)%4
//            (that stage was consumed last iter by everyone) -> compute kt%4.
#define GS 4                         // ring stages
#define G_LDS 40                     // BK + 8 pad (80B rows, LDSM conflict-free)
#define G_STAGE_E (128 * G_LDS)      // elems per stage per operand
#define G_SMEM (2 * GS * G_STAGE_E * 2)   // bytes total = 81920

template<bool BIAS_M, bool BIAS_N, bool HAS_RES, bool OUT_BF>
__global__ __launch_bounds__(256, 2)
void gemm_pipe(const bf16* __restrict__ A, const bf16* __restrict__ B,
               const float* __restrict__ biasM, const float* __restrict__ biasN,
               const float* __restrict__ res, void* __restrict__ Cp,
               int N, int K, int lda, int ldb,
               size_t strideA, size_t strideB, size_t strideC, size_t strideRes,
               float alpha)
{
    constexpr int BK = 32;
    extern __shared__ __align__(16) bf16 sm[];
    bf16* As = sm;                       // [GS][128][G_LDS]
    bf16* Bs = sm + GS * G_STAGE_E;

    const int tid  = threadIdx.x;
    const int lane = tid & 31;
    const int warp = tid >> 5;
    const int wm = warp & 1;
    const int wn = warp >> 1;
    const int g   = lane >> 2;
    const int tg2 = (lane & 3) * 2;

    const int batch = blockIdx.z;
    const int m0 = blockIdx.y * 128;
    const int n0 = blockIdx.x * 128;

    // staging map: row = tid>>2 (0..63, +64 second), 16B chunk = tid&3
    const int srow = tid >> 2;
    const int sch  = tid & 3;
    const bf16* Ag = A + batch * strideA + (size_t)(m0 + srow) * lda + sch * 8;
    const bf16* Bg = B + batch * strideB + (size_t)(n0 + srow) * ldb + sch * 8;
    const uint32_t aB = smem_u32(&As[srow * G_LDS + sch * 8]);
    const uint32_t bB = smem_u32(&Bs[srow * G_LDS + sch * 8]);
    constexpr uint32_t STG = G_STAGE_E * 2;        // stage stride bytes (10240)
    constexpr uint32_t R64 = 64 * G_LDS * 2;       // +64 rows (5120)

    const int nk = K / BK;

    // prologue: chunks 0..GS-2 into stages 0..GS-2
    #pragma unroll
    for (int s = 0; s < GS - 1; s++) {
        const bf16* Ak = Ag + s * BK;
        const bf16* Bk = Bg + s * BK;
        CP_ASYNC16(aB + s * STG,       Ak);
        CP_ASYNC16(aB + s * STG + R64, Ak + (size_t)64 * lda);
        CP_ASYNC16(bB + s * STG,       Bk);
        CP_ASYNC16(bB + s * STG + R64, Bk + (size_t)64 * ldb);
        CP_COMMIT();
    }

    float acc[4][4][4];
    #pragma unroll
    for (int i = 0; i < 4; i++)
        #pragma unroll
        for (int j = 0; j < 4; j++)
            #pragma unroll
            for (int r = 0; r < 4; r++) acc[i][j][r] = 0.f;

    const int arow = (lane & 15);
    const int acol = ((lane >> 4) & 1) * 8;
    const int brow = (lane & 7) + ((lane >> 4) << 3);
    const int bcol = ((lane >> 3) & 1) * 8;

    for (int kt = 0; kt < nk; kt++) {
        CP_WAIT2();                       // chunk kt resident
        __syncthreads();                  // all consumed stage (kt-1)%GS last iter

        // prefetch chunk kt+GS-1 into stage (kt+GS-1)%GS == (kt-1)%GS
        {
            const int pf = kt + GS - 1;
            if (pf < nk) {
                const int ps = pf & (GS - 1);
                const bf16* Ak = Ag + pf * BK;
                const bf16* Bk = Bg + pf * BK;
                CP_ASYNC16(aB + ps * STG,       Ak);
                CP_ASYNC16(aB + ps * STG + R64, Ak + (size_t)64 * lda);
                CP_ASYNC16(bB + ps * STG,       Bk);
                CP_ASYNC16(bB + ps * STG + R64, Bk + (size_t)64 * ldb);
            }
            CP_COMMIT();                  // commit even if empty (group order)
        }

        const int buf = kt & (GS - 1);
        const bf16* Ab = As + buf * G_STAGE_E;
        const bf16* Bb = Bs + buf * G_STAGE_E;

        #pragma unroll
        for (int ks = 0; ks < 2; ks++) {
            const int kb = ks * 16;
            uint32_t a[4][4];
            #pragma unroll
            for (int mt = 0; mt < 4; mt++) {
                uint32_t addr = smem_u32(&Ab[(wm * 64 + mt * 16 + arow) * G_LDS + kb + acol]);
                asm volatile("ldmatrix.sync.aligned.m8n8.x4.shared.b16 {%0,%1,%2,%3}, [%4];\n"
                             : "=r"(a[mt][0]), "=r"(a[mt][1]), "=r"(a[mt][2]), "=r"(a[mt][3])
                             : "r"(addr));
            }
            uint32_t b[4][2];
            #pragma unroll
            for (int np = 0; np < 2; np++) {
                uint32_t addr = smem_u32(&Bb[(wn * 32 + np * 16 + brow) * G_LDS + kb + bcol]);
                uint32_t r0, r1, r2, r3;
                asm volatile("ldmatrix.sync.aligned.m8n8.x4.shared.b16 {%0,%1,%2,%3}, [%4];\n"
                             : "=r"(r0), "=r"(r1), "=r"(r2), "=r"(r3)
                             : "r"(addr));
                b[np * 2 + 0][0] = r0; b[np * 2 + 0][1] = r1;
                b[np * 2 + 1][0] = r2; b[np * 2 + 1][1] = r3;
            }
            #pragma unroll
            for (int mt = 0; mt < 4; mt++)
                #pragma unroll
                for (int nt = 0; nt < 4; nt++) {
                    asm volatile(
                        "mma.sync.aligned.m16n8k16.row.col.f32.bf16.bf16.f32 "
                        "{%0,%1,%2,%3}, {%4,%5,%6,%7}, {%8,%9}, {%0,%1,%2,%3};\n"
                        : "+f"(acc[mt][nt][0]), "+f"(acc[mt][nt][1]),
                          "+f"(acc[mt][nt][2]), "+f"(acc[mt][nt][3])
                        : "r"(a[mt][0]), "r"(a[mt][1]), "r"(a[mt][2]), "r"(a[mt][3]),
                          "r"(b[nt][0]), "r"(b[nt][1]));
                }
        }
    }

    // ---- epilogue
    const float* Rb = HAS_RES ? (res + batch * strideRes) : nullptr;
    #pragma unroll
    for (int mt = 0; mt < 4; mt++) {
        int row = m0 + wm * 64 + mt * 16 + g;
        float bm0 = BIAS_M ? biasM[row]     : 0.f;
        float bm1 = BIAS_M ? biasM[row + 8] : 0.f;
        #pragma unroll
        for (int nt = 0; nt < 4; nt++) {
            int col = n0 + wn * 32 + nt * 8 + tg2;
            float2 v0, v1;
            v0.x = alpha * acc[mt][nt][0] + bm0;
            v0.y = alpha * acc[mt][nt][1] + bm0;
            v1.x = alpha * acc[mt][nt][2] + bm1;
            v1.y = alpha * acc[mt][nt][3] + bm1;
            if (BIAS_N) {
                float2 bn = *(const float2*)&biasN[col];
                v0.x += bn.x; v0.y += bn.y;
                v1.x += bn.x; v1.y += bn.y;
            }
            if (HAS_RES) {
                float2 r0 = *(const float2*)&Rb[(size_t)row * N + col];
                float2 r1 = *(const float2*)&Rb[(size_t)(row + 8) * N + col];
                v0.x += r0.x; v0.y += r0.y;
                v1.x += r1.x; v1.y += r1.y;
            }
            if (OUT_BF) {
                bf16* Cb = (bf16*)Cp + batch * strideC;
                *(uint32_t*)&Cb[(size_t)row * N + col]       = packbf(v0.x, v0.y);
                *(uint32_t*)&Cb[(size_t)(row + 8) * N + col] = packbf(v1.x, v1.y);
            } else {
                float* Cb = (float*)Cp + batch * strideC;
                *(float2*)&Cb[(size_t)row * N + col]       = v0;
                *(float2*)&Cb[(size_t)(row + 8) * N + col] = v1;
            }
        }
    }
}

// ---------------- Row softmax: fp32 in -> bf16 out ---------------------------
__global__ __launch_bounds__(256)
void softmax_kernel(const float* __restrict__ attn, bf16* __restrict__ attnbf)
{
    const float* row = attn + (size_t)blockIdx.x * HW;
    bf16* orow = attnbf + (size_t)blockIdx.x * HW;
    const int tid = threadIdx.x;
    float4 v = ((const float4*)row)[tid];

    float mx = fmaxf(fmaxf(v.x, v.y), fmaxf(v.z, v.w));
    __shared__ float sred[8];
    int lane = tid & 31, wid = tid >> 5;
    #pragma unroll
    for (int o = 16; o > 0; o >>= 1) mx = fmaxf(mx, __shfl_xor_sync(0xffffffffu, mx, o));
    if (lane == 0) sred[wid] = mx;
    __syncthreads();
    if (wid == 0) {
        mx = sred[lane & 7];
        #pragma unroll
        for (int o = 4; o > 0; o >>= 1) mx = fmaxf(mx, __shfl_xor_sync(0xffffffffu, mx, o));
        if (lane == 0) sred[0] = mx;
    }
    __syncthreads();
    mx = sred[0];

    v.x = __expf(v.x - mx); v.y = __expf(v.y - mx);
    v.z = __expf(v.z - mx); v.w = __expf(v.w - mx);
    float sum = v.x + v.y + v.z + v.w;
    #pragma unroll
    for (int o = 16; o > 0; o >>= 1) sum += __shfl_xor_sync(0xffffffffu, sum, o);
    if (lane == 0) sred[wid] = sum;
    __syncthreads();
    if (wid == 0) {
        sum = sred[lane & 7];
        #pragma unroll
        for (int o = 4; o > 0; o >>= 1) sum += __shfl_xor_sync(0xffffffffu, sum, o);
        if (lane == 0) sred[0] = sum;
    }
    __syncthreads();
    float inv = 1.f / sred[0];
    uint2 o = make_uint2(packbf(v.x * inv, v.y * inv), packbf(v.z * inv, v.w * inv));
    ((uint2*)orow)[tid] = o;
}

// ---------------- launch ------------------------------------------------------
extern "C" void kernel_launch(void* const* d_in, const int* in_sizes, int n_in,
                              void* d_out, int out_size)
{
    const float* x      = (const float*)d_in[0];
    const float* gn_w   = (const float*)d_in[1];
    const float* gn_b   = (const float*)d_in[2];
    const float* qkv_w  = (const float*)d_in[3];
    const float* qkv_b  = (const float*)d_in[4];
    const float* proj_w = (const float*)d_in[5];
    const float* proj_b = (const float*)d_in[6];
    float* out = (float*)d_out;

    bf16 *xnT, *qkT, *v, *attnbf, *aoutT, *wbf, *pwbf;
    float *attn;
    cudaGetSymbolAddress((void**)&xnT,    g_xnT);
    cudaGetSymbolAddress((void**)&qkT,    g_qkT);
    cudaGetSymbolAddress((void**)&v,      g_v);
    cudaGetSymbolAddress((void**)&attn,   g_attn);
    cudaGetSymbolAddress((void**)&attnbf, g_attnbf);
    cudaGetSymbolAddress((void**)&aoutT,  g_aoutT);
    cudaGetSymbolAddress((void**)&wbf,    g_wbf);
    cudaGetSymbolAddress((void**)&pwbf,   g_pwbf);

    cudaFuncSetAttribute(gemm_pipe<false, true,  false, true >, cudaFuncAttributeMaxDynamicSharedMemorySize, G_SMEM);
    cudaFuncSetAttribute(gemm_pipe<true,  false, false, true >, cudaFuncAttributeMaxDynamicSharedMemorySize, G_SMEM);
    cudaFuncSetAttribute(gemm_pipe<false, false, false, false>, cudaFuncAttributeMaxDynamicSharedMemorySize, G_SMEM);
    cudaFuncSetAttribute(gemm_pipe<false, false, false, true >, cudaFuncAttributeMaxDynamicSharedMemorySize, G_SMEM);
    cudaFuncSetAttribute(gemm_pipe<true,  false, true,  false>, cudaFuncAttributeMaxDynamicSharedMemorySize, G_SMEM);

    const size_t sNC  = (size_t)HW * CH;        // [pix][c] tensors
    const size_t sQK  = (size_t)HW * 2 * CH;    // qkT per-batch stride
    const size_t sCN  = (size_t)CH * HW;        // [c][pix] tensors
    const size_t sATT = (size_t)HW * HW;
    const float scale = rsqrtf((float)CH);

    // 0) weights -> bf16
    tobf16_kernel<<<(3 * CH * CH / 4 + 255) / 256, 256>>>(qkv_w, wbf, 3 * CH * CH / 4);
    tobf16_kernel<<<(CH * CH / 4 + 255) / 256, 256>>>(proj_w, pwbf, CH * CH / 4);

    // 1) GroupNorm -> xnT bf16 [b][pix][c]
    groupnorm_t_kernel<<<BATCH * NG, 256>>>(x, gn_w, gn_b, xnT);

    // 2) fused Q|K: qkT[i][co] = xnT[i][c] . W[co][c] + qkv_b[co], co in [0,1024)
    {
        dim3 grid(2 * CH / 128, HW / 128, BATCH);
        gemm_pipe<false, true, false, true><<<grid, 256, G_SMEM>>>(
            xnT, wbf, nullptr, qkv_b, nullptr, qkT,
            2 * CH, CH, CH, CH, sNC, 0, sQK, 0, 1.0f);
    }
    // 3) V[co][j] = Wv[co][c] . xnT[j][c] + qkv_b[2CH+co]
    {
        dim3 grid(HW / 128, CH / 128, BATCH);
        gemm_pipe<true, false, false, true><<<grid, 256, G_SMEM>>>(
            wbf + (size_t)2 * CH * CH, xnT, qkv_b + 2 * CH, nullptr, nullptr, v,
            HW, CH, CH, CH, 0, sNC, sCN, 0, 1.0f);
    }
    // 4) S[i][j] = scale * Q[i][c] . K[j][c]   (fp32 out)
    {
        dim3 grid(HW / 128, HW / 128, BATCH);
        gemm_pipe<false, false, false, false><<<grid, 256, G_SMEM>>>(
            qkT, qkT + CH, nullptr, nullptr, nullptr, attn,
            HW, CH, 2 * CH, 2 * CH, sQK, sQK, sATT, 0, scale);
    }
    // 5) softmax rows -> bf16
    softmax_kernel<<<BATCH * HW, 256>>>(attn, attnbf);

    // 6) aoutT[i][c] = attnbf[i][j] . V[c][j]
    {
        dim3 grid(CH / 128, HW / 128, BATCH);
        gemm_pipe<false, false, false, true><<<grid, 256, G_SMEM>>>(
            attnbf, v, nullptr, nullptr, nullptr, aoutT,
            CH, HW, HW, HW, sATT, sCN, sNC, 0, 1.0f);
    }
    // 7) out[co][pix] = P[co][c] . aoutT[pix][c] + proj_b[co] + x  (fp32 out)
    {
        dim3 grid(HW / 128, CH / 128, BATCH);
        gemm_pipe<true, false, true, false><<<grid, 256, G_SMEM>>>(
            pwbf, aoutT, proj_b, nullptr, x, out,
            HW, CH, CH, CH, 0, sNC, sCN, sCN, 1.0f);
    }
}

// round 10
// speedup vs baseline: 1.0671x; 1.0671x over previous
#include <cuda_runtime.h>
#include <cuda_bf16.h>
#include <stdint.h>
#include <math.h>

// Problem constants (fixed by the reference)
#define BATCH 8
#define CH    512
#define HW    1024       // 32*32 spatial
#define NG    32
#define CPG   16
#define GRP_ELEMS (CPG*HW)   // 16384

typedef __nv_bfloat16 bf16;

// ---------------- scratch (static device globals; no allocation) -------------
__device__ bf16  g_xnT   [BATCH * HW * CH];        // xn^T  [b][pix][c]
__device__ bf16  g_qkT   [BATCH * HW * 2 * CH];    // [b][i][0..511]=Q, [512..1023]=K
__device__ bf16  g_v     [BATCH * CH * HW];        // V     [b][c][j]
__device__ float g_attn  [BATCH * HW * HW];        // scores fp32 [b][i][j]
__device__ bf16  g_attnbf[BATCH * HW * HW];        // softmaxed, bf16
__device__ bf16  g_aoutT [BATCH * HW * CH];        // out^T [b][i][c]
__device__ bf16  g_wbf   [3 * CH * CH];            // qkv_w bf16
__device__ bf16  g_pwbf  [CH * CH];                // proj_w bf16

// ---------------- helpers -----------------------------------------------------
__device__ __forceinline__ uint32_t packbf(float x, float y) {
    __nv_bfloat162 h = __float22bfloat162_rn(make_float2(x, y));
    return *(uint32_t*)&h;
}
__device__ __forceinline__ uint32_t smem_u32(const void* p) {
    return (uint32_t)__cvta_generic_to_shared(p);
}
#define CP_ASYNC16(dst, src) \
    asm volatile("cp.async.cg.shared.global [%0], [%1], 16;\n" :: "r"(dst), "l"(src))
#define CP_COMMIT()  asm volatile("cp.async.commit_group;\n" ::)
#define CP_WAIT1()   asm volatile("cp.async.wait_group 1;\n" ::)

// ---------------- weight conversion f32 -> bf16 ------------------------------
__global__ void tobf16_kernel(const float* __restrict__ in, bf16* __restrict__ out, int n4)
{
    int i = blockIdx.x * blockDim.x + threadIdx.x;
    if (i < n4) {
        float4 v = ((const float4*)in)[i];
        uint2 o = make_uint2(packbf(v.x, v.y), packbf(v.z, v.w));
        ((uint2*)out)[i] = o;
    }
}

// ---------------- GroupNorm (writes transposed bf16 xnT) ---------------------
__global__ __launch_bounds__(256)
void groupnorm_t_kernel(const float* __restrict__ x,
                        const float* __restrict__ w,
                        const float* __restrict__ bias,
                        bf16* __restrict__ xnT)
{
    const int bg = blockIdx.x;
    const int b  = bg / NG;
    const int g  = bg % NG;
    const float* xp = x + ((size_t)b * CH + (size_t)g * CPG) * HW;

    const int tid = threadIdx.x;
    float sum = 0.f, sq = 0.f;
    for (int i = tid; i < GRP_ELEMS; i += 256) {
        float v = xp[i];
        sum += v; sq += v * v;
    }
    __shared__ float ssum[8], ssq[8];
    int lane = tid & 31, wid = tid >> 5;
    #pragma unroll
    for (int o = 16; o > 0; o >>= 1) {
        sum += __shfl_xor_sync(0xffffffffu, sum, o);
        sq  += __shfl_xor_sync(0xffffffffu, sq,  o);
    }
    if (lane == 0) { ssum[wid] = sum; ssq[wid] = sq; }
    __syncthreads();
    if (wid == 0) {
        sum = ssum[lane & 7];
        sq  = ssq [lane & 7];
        #pragma unroll
        for (int o = 4; o > 0; o >>= 1) {
            sum += __shfl_xor_sync(0xffffffffu, sum, o);
            sq  += __shfl_xor_sync(0xffffffffu, sq,  o);
        }
        if (lane == 0) { ssum[0] = sum; ssq[0] = sq; }
    }
    __syncthreads();
    const float inv_n = 1.f / (float)GRP_ELEMS;
    const float mean  = ssum[0] * inv_n;
    const float var   = ssq[0] * inv_n - mean * mean;
    const float rstd  = rsqrtf(var + 1e-5f);

    __shared__ float tile[CPG][64 + 1];
    for (int pt = 0; pt < 16; pt++) {
        __syncthreads();
        #pragma unroll
        for (int j = 0; j < 4; j++) {
            int e = tid + j * 256;
            int c = e >> 6, p = e & 63;
            float v = xp[c * HW + pt * 64 + p];
            tile[c][p] = (v - mean) * rstd * w[g * CPG + c] + bias[g * CPG + c];
        }
        __syncthreads();
        int p = tid >> 2, cq = tid & 3;
        uint2 o = make_uint2(packbf(tile[cq * 4 + 0][p], tile[cq * 4 + 1][p]),
                             packbf(tile[cq * 4 + 2][p], tile[cq * 4 + 3][p]));
        *(uint2*)&xnT[((size_t)b * HW + pt * 64 + p) * CH + g * CPG + cq * 4] = o;
    }
}

// ---------------- pipelined bf16 tensor-core GEMM ----------------------------
// C[b][m][n] = alpha * sum_k A[m][k]*B[n][k]  (+biasM[m]) (+biasN[n]) (+res)
// A bf16 [M x K] (lda), B bf16 [N x K] (ldb), C (ldc = N) fp32 or bf16.
// Tiles BM=BN=128, BK=64; 8 warps (2M x 4N), warp tile 64x32, mma.m16n8k16.
// 3-stage cp.async ring, ONE __syncthreads per 64-k iteration.
#define GS 3                          // ring stages
#define G_LDS 72                      // BK + 8 pad (144B rows, LDSM conflict-free)
#define G_STAGE_E (128 * G_LDS)       // elems per stage per operand (9216)
#define G_SMEM (2 * GS * G_STAGE_E * 2)   // bytes total = 110592

template<bool BIAS_M, bool BIAS_N, bool HAS_RES, bool OUT_BF>
__global__ __launch_bounds__(256, 2)
void gemm_pipe(const bf16* __restrict__ A, const bf16* __restrict__ B,
               const float* __restrict__ biasM, const float* __restrict__ biasN,
               const float* __restrict__ res, void* __restrict__ Cp,
               int N, int K, int lda, int ldb,
               size_t strideA, size_t strideB, size_t strideC, size_t strideRes,
               float alpha)
{
    constexpr int BK = 64;
    extern __shared__ __align__(16) bf16 sm[];
    bf16* As = sm;                       // [GS][128][G_LDS]
    bf16* Bs = sm + GS * G_STAGE_E;

    const int tid  = threadIdx.x;
    const int lane = tid & 31;
    const int warp = tid >> 5;
    const int wm = warp & 1;
    const int wn = warp >> 1;
    const int g   = lane >> 2;
    const int tg2 = (lane & 3) * 2;

    const int batch = blockIdx.z;
    const int m0 = blockIdx.y * 128;
    const int n0 = blockIdx.x * 128;

    // staging map: row = tid>>3 (0..31, +32 per pass p), 16B chunk = tid&7
    const int srow = tid >> 3;
    const int sch  = tid & 7;
    const bf16* Ag = A + batch * strideA + (size_t)(m0 + srow) * lda + sch * 8;
    const bf16* Bg = B + batch * strideB + (size_t)(n0 + srow) * ldb + sch * 8;
    const uint32_t aB = smem_u32(&As[srow * G_LDS + sch * 8]);
    const uint32_t bB = smem_u32(&Bs[srow * G_LDS + sch * 8]);
    constexpr uint32_t STG = G_STAGE_E * 2;        // stage stride bytes (18432)
    constexpr uint32_t R32 = 32 * G_LDS * 2;       // +32 rows (4608)

    const int nk = K / BK;

    // prologue: chunks 0..GS-2 into stages 0..GS-2
    #pragma unroll
    for (int s = 0; s < GS - 1; s++) {
        const bf16* Ak = Ag + s * BK;
        const bf16* Bk = Bg + s * BK;
        #pragma unroll
        for (int p = 0; p < 4; p++) {
            CP_ASYNC16(aB + s * STG + p * R32, Ak + (size_t)(32 * p) * lda);
            CP_ASYNC16(bB + s * STG + p * R32, Bk + (size_t)(32 * p) * ldb);
        }
        CP_COMMIT();
    }

    float acc[4][4][4];
    #pragma unroll
    for (int i = 0; i < 4; i++)
        #pragma unroll
        for (int j = 0; j < 4; j++)
            #pragma unroll
            for (int r = 0; r < 4; r++) acc[i][j][r] = 0.f;

    const int arow = (lane & 15);
    const int acol = ((lane >> 4) & 1) * 8;
    const int brow = (lane & 7) + ((lane >> 4) << 3);
    const int bcol = ((lane >> 3) & 1) * 8;

    for (int kt = 0; kt < nk; kt++) {
        CP_WAIT1();                       // chunk kt resident
        __syncthreads();                  // stage (kt-1)%GS fully consumed

        // prefetch chunk kt+GS-1 into stage (kt+GS-1)%GS == (kt-1)%GS
        {
            const int pf = kt + GS - 1;
            if (pf < nk) {
                const int ps = pf % GS;
                const bf16* Ak = Ag + pf * BK;
                const bf16* Bk = Bg + pf * BK;
                #pragma unroll
                for (int p = 0; p < 4; p++) {
                    CP_ASYNC16(aB + ps * STG + p * R32, Ak + (size_t)(32 * p) * lda);
                    CP_ASYNC16(bB + ps * STG + p * R32, Bk + (size_t)(32 * p) * ldb);
                }
            }
            CP_COMMIT();                  // commit even if empty (group order)
        }

        const int buf = kt % GS;
        const bf16* Ab = As + buf * G_STAGE_E;
        const bf16* Bb = Bs + buf * G_STAGE_E;

        #pragma unroll
        for (int ks = 0; ks < 4; ks++) {
            const int kb = ks * 16;
            uint32_t a[4][4];
            #pragma unroll
            for (int mt = 0; mt < 4; mt++) {
                uint32_t addr = smem_u32(&Ab[(wm * 64 + mt * 16 + arow) * G_LDS + kb + acol]);
                asm volatile("ldmatrix.sync.aligned.m8n8.x4.shared.b16 {%0,%1,%2,%3}, [%4];\n"
                             : "=r"(a[mt][0]), "=r"(a[mt][1]), "=r"(a[mt][2]), "=r"(a[mt][3])
                             : "r"(addr));
            }
            uint32_t b[4][2];
            #pragma unroll
            for (int np = 0; np < 2; np++) {
                uint32_t addr = smem_u32(&Bb[(wn * 32 + np * 16 + brow) * G_LDS + kb + bcol]);
                uint32_t r0, r1, r2, r3;
                asm volatile("ldmatrix.sync.aligned.m8n8.x4.shared.b16 {%0,%1,%2,%3}, [%4];\n"
                             : "=r"(r0), "=r"(r1), "=r"(r2), "=r"(r3)
                             : "r"(addr));
                b[np * 2 + 0][0] = r0; b[np * 2 + 0][1] = r1;
                b[np * 2 + 1][0] = r2; b[np * 2 + 1][1] = r3;
            }
            #pragma unroll
            for (int mt = 0; mt < 4; mt++)
                #pragma unroll
                for (int nt = 0; nt < 4; nt++) {
                    asm volatile(
                        "mma.sync.aligned.m16n8k16.row.col.f32.bf16.bf16.f32 "
                        "{%0,%1,%2,%3}, {%4,%5,%6,%7}, {%8,%9}, {%0,%1,%2,%3};\n"
                        : "+f"(acc[mt][nt][0]), "+f"(acc[mt][nt][1]),
                          "+f"(acc[mt][nt][2]), "+f"(acc[mt][nt][3])
                        : "r"(a[mt][0]), "r"(a[mt][1]), "r"(a[mt][2]), "r"(a[mt][3]),
                          "r"(b[nt][0]), "r"(b[nt][1]));
                }
        }
    }

    // ---- epilogue
    const float* Rb = HAS_RES ? (res + batch * strideRes) : nullptr;
    #pragma unroll
    for (int mt = 0; mt < 4; mt++) {
        int row = m0 + wm * 64 + mt * 16 + g;
        float bm0 = BIAS_M ? biasM[row]     : 0.f;
        float bm1 = BIAS_M ? biasM[row + 8] : 0.f;
        #pragma unroll
        for (int nt = 0; nt < 4; nt++) {
            int col = n0 + wn * 32 + nt * 8 + tg2;
            float2 v0, v1;
            v0.x = alpha * acc[mt][nt][0] + bm0;
            v0.y = alpha * acc[mt][nt][1] + bm0;
            v1.x = alpha * acc[mt][nt][2] + bm1;
            v1.y = alpha * acc[mt][nt][3] + bm1;
            if (BIAS_N) {
                float2 bn = *(const float2*)&biasN[col];
                v0.x += bn.x; v0.y += bn.y;
                v1.x += bn.x; v1.y += bn.y;
            }
            if (HAS_RES) {
                float2 r0 = *(const float2*)&Rb[(size_t)row * N + col];
                float2 r1 = *(const float2*)&Rb[(size_t)(row + 8) * N + col];
                v0.x += r0.x; v0.y += r0.y;
                v1.x += r1.x; v1.y += r1.y;
            }
            if (OUT_BF) {
                bf16* Cb = (bf16*)Cp + batch * strideC;
                *(uint32_t*)&Cb[(size_t)row * N + col]       = packbf(v0.x, v0.y);
                *(uint32_t*)&Cb[(size_t)(row + 8) * N + col] = packbf(v1.x, v1.y);
            } else {
                float* Cb = (float*)Cp + batch * strideC;
                *(float2*)&Cb[(size_t)row * N + col]       = v0;
                *(float2*)&Cb[(size_t)(row + 8) * N + col] = v1;
            }
        }
    }
}

// ---------------- Row softmax: warp-per-row, fp32 in -> bf16 out -------------
// 8 warps/block, each warp owns one full row of 1024; shuffle-only reductions.
__global__ __launch_bounds__(256)
void softmax_kernel(const float* __restrict__ attn, bf16* __restrict__ attnbf)
{
    const int warp = threadIdx.x >> 5;
    const int lane = threadIdx.x & 31;
    const size_t row = (size_t)blockIdx.x * 8 + warp;
    const float4* rp = (const float4*)(attn + row * HW);
    uint2* op = (uint2*)(attnbf + row * HW);

    float4 v[8];
    float mx = -3.4e38f;
    #pragma unroll
    for (int i = 0; i < 8; i++) {
        v[i] = rp[lane + i * 32];
        mx = fmaxf(mx, fmaxf(fmaxf(v[i].x, v[i].y), fmaxf(v[i].z, v[i].w)));
    }
    #pragma unroll
    for (int o = 16; o > 0; o >>= 1) mx = fmaxf(mx, __shfl_xor_sync(0xffffffffu, mx, o));

    float sum = 0.f;
    #pragma unroll
    for (int i = 0; i < 8; i++) {
        v[i].x = __expf(v[i].x - mx); v[i].y = __expf(v[i].y - mx);
        v[i].z = __expf(v[i].z - mx); v[i].w = __expf(v[i].w - mx);
        sum += (v[i].x + v[i].y) + (v[i].z + v[i].w);
    }
    #pragma unroll
    for (int o = 16; o > 0; o >>= 1) sum += __shfl_xor_sync(0xffffffffu, sum, o);

    const float inv = 1.f / sum;
    #pragma unroll
    for (int i = 0; i < 8; i++) {
        uint2 o2 = make_uint2(packbf(v[i].x * inv, v[i].y * inv),
                              packbf(v[i].z * inv, v[i].w * inv));
        op[lane + i * 32] = o2;
    }
}

// ---------------- launch ------------------------------------------------------
extern "C" void kernel_launch(void* const* d_in, const int* in_sizes, int n_in,
                              void* d_out, int out_size)
{
    const float* x      = (const float*)d_in[0];
    const float* gn_w   = (const float*)d_in[1];
    const float* gn_b   = (const float*)d_in[2];
    const float* qkv_w  = (const float*)d_in[3];
    const float* qkv_b  = (const float*)d_in[4];
    const float* proj_w = (const float*)d_in[5];
    const float* proj_b = (const float*)d_in[6];
    float* out = (float*)d_out;

    bf16 *xnT, *qkT, *v, *attnbf, *aoutT, *wbf, *pwbf;
    float *attn;
    cudaGetSymbolAddress((void**)&xnT,    g_xnT);
    cudaGetSymbolAddress((void**)&qkT,    g_qkT);
    cudaGetSymbolAddress((void**)&v,      g_v);
    cudaGetSymbolAddress((void**)&attn,   g_attn);
    cudaGetSymbolAddress((void**)&attnbf, g_attnbf);
    cudaGetSymbolAddress((void**)&aoutT,  g_aoutT);
    cudaGetSymbolAddress((void**)&wbf,    g_wbf);
    cudaGetSymbolAddress((void**)&pwbf,   g_pwbf);

    cudaFuncSetAttribute(gemm_pipe<false, true,  false, true >, cudaFuncAttributeMaxDynamicSharedMemorySize, G_SMEM);
    cudaFuncSetAttribute(gemm_pipe<true,  false, false, true >, cudaFuncAttributeMaxDynamicSharedMemorySize, G_SMEM);
    cudaFuncSetAttribute(gemm_pipe<false, false, false, false>, cudaFuncAttributeMaxDynamicSharedMemorySize, G_SMEM);
    cudaFuncSetAttribute(gemm_pipe<false, false, false, true >, cudaFuncAttributeMaxDynamicSharedMemorySize, G_SMEM);
    cudaFuncSetAttribute(gemm_pipe<true,  false, true,  false>, cudaFuncAttributeMaxDynamicSharedMemorySize, G_SMEM);

    const size_t sNC  = (size_t)HW * CH;        // [pix][c] tensors
    const size_t sQK  = (size_t)HW * 2 * CH;    // qkT per-batch stride
    const size_t sCN  = (size_t)CH * HW;        // [c][pix] tensors
    const size_t sATT = (size_t)HW * HW;
    const float scale = rsqrtf((float)CH);

    // 0) weights -> bf16
    tobf16_kernel<<<(3 * CH * CH / 4 + 255) / 256, 256>>>(qkv_w, wbf, 3 * CH * CH / 4);
    tobf16_kernel<<<(CH * CH / 4 + 255) / 256, 256>>>(proj_w, pwbf, CH * CH / 4);

    // 1) GroupNorm -> xnT bf16 [b][pix][c]
    groupnorm_t_kernel<<<BATCH * NG, 256>>>(x, gn_w, gn_b, xnT);

    // 2) fused Q|K: qkT[i][co] = xnT[i][c] . W[co][c] + qkv_b[co], co in [0,1024)
    {
        dim3 grid(2 * CH / 128, HW / 128, BATCH);
        gemm_pipe<false, true, false, true><<<grid, 256, G_SMEM>>>(
            xnT, wbf, nullptr, qkv_b, nullptr, qkT,
            2 * CH, CH, CH, CH, sNC, 0, sQK, 0, 1.0f);
    }
    // 3) V[co][j] = Wv[co][c] . xnT[j][c] + qkv_b[2CH+co]
    {
        dim3 grid(HW / 128, CH / 128, BATCH);
        gemm_pipe<true, false, false, true><<<grid, 256, G_SMEM>>>(
            wbf + (size_t)2 * CH * CH, xnT, qkv_b + 2 * CH, nullptr, nullptr, v,
            HW, CH, CH, CH, 0, sNC, sCN, 0, 1.0f);
    }
    // 4) S[i][j] = scale * Q[i][c] . K[j][c]   (fp32 out)
    {
        dim3 grid(HW / 128, HW / 128, BATCH);
        gemm_pipe<false, false, false, false><<<grid, 256, G_SMEM>>>(
            qkT, qkT + CH, nullptr, nullptr, nullptr, attn,
            HW, CH, 2 * CH, 2 * CH, sQK, sQK, sATT, 0, scale);
    }
    // 5) softmax rows -> bf16 (warp per row)
    softmax_kernel<<<BATCH * HW / 8, 256>>>(attn, attnbf);

    // 6) aoutT[i][c] = attnbf[i][j] . V[c][j]
    {
        dim3 grid(CH / 128, HW / 128, BATCH);
        gemm_pipe<false, false, false, true><<<grid, 256, G_SMEM>>>(
            attnbf, v, nullptr, nullptr, nullptr, aoutT,
            CH, HW, HW, HW, sATT, sCN, sNC, 0, 1.0f);
    }
    // 7) out[co][pix] = P[co][c] . aoutT[pix][c] + proj_b[co] + x  (fp32 out)
    {
        dim3 grid(HW / 128, CH / 128, BATCH);
        gemm_pipe<true, false, true, false><<<grid, 256, G_SMEM>>>(
            pwbf, aoutT, proj_b, nullptr, x, out,
            HW, CH, CH, CH, 0, sNC, sCN, sCN, 1.0f);
    }
}